// round 13
// baseline (speedup 1.0000x reference)
#include <cuda_runtime.h>
#include <cstdint>

#define TBLOCK  128
#define NWARP   4
#define NFILT   11
#define NCOLS   262144
#define NROWS   128
#define WTILE   128                 // outputs per warp-tile
#define TPW     4                   // tiles per warp (pipelined chain)
#define STAGES  4
#define CHUNKS  72                  // float4 chunks per tile: complexes [T0-6, T0+138)
#define NF4ROW  (NCOLS / 2)

typedef unsigned long long u64;

__device__ __forceinline__ u64 pack2(float lo, float hi) {
    u64 r; asm("mov.b64 %0, {%1, %2};" : "=l"(r) : "f"(lo), "f"(hi)); return r;
}
__device__ __forceinline__ void unpack2(u64 v, float& lo, float& hi) {
    asm("mov.b64 {%0, %1}, %2;" : "=f"(lo), "=f"(hi) : "l"(v));
}
__device__ __forceinline__ u64 fma2(u64 a, u64 b, u64 c) {
    u64 d; asm("fma.rn.f32x2 %0, %1, %2, %3;" : "=l"(d) : "l"(a), "l"(b), "l"(c)); return d;
}
__device__ __forceinline__ void cpa16(uint32_t s, const float4* g) {
    asm volatile("cp.async.cg.shared.global [%0], [%1], 16;" :: "r"(s), "l"(g));
}
__device__ __forceinline__ void cpa_commit() {
    asm volatile("cp.async.commit_group;");
}
template <int N> __device__ __forceinline__ void cpa_wait() {
    asm volatile("cp.async.wait_group %0;" :: "n"(N));
}
// Swizzle chunk index so stride-2 reads (d = 2*lane + q) are bank-conflict-free.
__device__ __forceinline__ int swz(int d) { return d ^ ((d >> 3) & 1); }

__global__ void __launch_bounds__(TBLOCK, 11) fir_cpdeep_kernel(
    const float2* __restrict__ X, const float* __restrict__ phi,
    float2* __restrict__ Y)
{
    // Per-warp private 4-stage AoS ring. sbuf[w][s][swz(d)] holds gmem chunk g0+d.
    __shared__ __align__(16) float4 sbuf[NWARP][STAGES][CHUNKS];

    const int lane = threadIdx.x & 31;
    const int wid  = threadIdx.x >> 5;
    const int row  = blockIdx.y;
    const float4* x4 = (const float4*)(X + (size_t)row * NCOLS);
    float2* yrow     = Y + (size_t)row * NCOLS;

    // Coefficients A[k] = (wr_k, wi_k) — phi's native layout.
    u64 A[NFILT];
#pragma unroll
    for (int k = 0; k < NFILT; k++) {
        float2 w = __ldg(((const float2*)phi) + k);
        A[k] = pack2(w.x, w.y);
    }

    // Warp's chain: tiles [wt0, wt0+TPW), tile t covers cols [(wt0+t)*128, +128).
    const int wt0 = (blockIdx.x * NWARP + wid) * TPW;

    #define ISSUE_TILE(t) do {                                                     \
        const int g0  = (wt0 + (t)) * 64 - 3;                                      \
        float4* dst = &sbuf[wid][(t) & (STAGES - 1)][0];                           \
        {   const int d = lane;      const int u = g0 + d;                         \
            uint32_t a = (uint32_t)__cvta_generic_to_shared(&dst[swz(d)]);         \
            if (u >= 0 && u < NF4ROW) cpa16(a, x4 + u);                            \
            else dst[swz(d)] = make_float4(0.f, 0.f, 0.f, 0.f);                    \
        }                                                                          \
        {   const int d = lane + 32; const int u = g0 + d;                         \
            uint32_t a = (uint32_t)__cvta_generic_to_shared(&dst[swz(d)]);         \
            if (u >= 0 && u < NF4ROW) cpa16(a, x4 + u);                            \
            else dst[swz(d)] = make_float4(0.f, 0.f, 0.f, 0.f);                    \
        }                                                                          \
        if (lane < 8) {                                                            \
            const int d = lane + 64; const int u = g0 + d;                         \
            uint32_t a = (uint32_t)__cvta_generic_to_shared(&dst[swz(d)]);         \
            if (u >= 0 && u < NF4ROW) cpa16(a, x4 + u);                            \
            else dst[swz(d)] = make_float4(0.f, 0.f, 0.f, 0.f);                    \
        }                                                                          \
        cpa_commit();                                                              \
    } while (0)

    // Prologue: three tiles in flight.
    ISSUE_TILE(0);
    ISSUE_TILE(1);
    ISSUE_TILE(2);

#pragma unroll
    for (int it = 0; it < TPW; ++it) {
        // Tile `it` must be complete. Issued: tiles 0..min(it+2, TPW-1).
        // Allowed outstanding after wait = min(2, TPW-1-it).
        if (it + 3 <= TPW)      cpa_wait<2>();
        else if (it + 2 == TPW) cpa_wait<1>();
        else                    cpa_wait<0>();
        __syncwarp();

        if (it + 3 < TPW) ISSUE_TILE(it + 3);   // stage (it+3)%4 — held tile it-1, done

        // ---- Compute tile `it` ----
        // Thread chunks d = 2*lane + q, q=0..7 -> rel complexes [4l, 4l+15] = w[0..15].
        // Output i (col T0 + 4l + i), tap k -> w[i + k + 1].
        const float4* base = &sbuf[wid][it & (STAGES - 1)][0];
        float re[16], im[16];
#pragma unroll
        for (int q = 0; q < 8; q++) {
            float4 v = base[swz(2 * lane + q)];
            re[2*q]   = v.x; im[2*q]   = v.y;
            re[2*q+1] = v.z; im[2*q+1] = v.w;
        }

        u64 P[4], Q[4];
#pragma unroll
        for (int i = 0; i < 4; i++) { P[i] = 0ull; Q[i] = 0ull; }

#pragma unroll
        for (int j = 1; j <= 14; j++) {
            u64 xrr = pack2(re[j], re[j]);
            u64 xii = pack2(im[j], im[j]);
#pragma unroll
            for (int i = 0; i < 4; i++) {
                const int k = j - 1 - i;            // compile-time after unroll
                if (k >= 0 && k < NFILT) {
                    P[i] = fma2(xrr, A[k], P[i]);
                    Q[i] = fma2(xii, A[k], Q[i]);
                }
            }
        }

        // out = (P.lo - Q.hi, P.hi + Q.lo)
        const int c0 = (wt0 + it) * WTILE + 4 * lane;
        float4 o0, o1;
        float prr, pri, qir, qii;
        unpack2(P[0], prr, pri); unpack2(Q[0], qir, qii); o0.x = prr - qii; o0.y = pri + qir;
        unpack2(P[1], prr, pri); unpack2(Q[1], qir, qii); o0.z = prr - qii; o0.w = pri + qir;
        unpack2(P[2], prr, pri); unpack2(Q[2], qir, qii); o1.x = prr - qii; o1.y = pri + qir;
        unpack2(P[3], prr, pri); unpack2(Q[3], qir, qii); o1.z = prr - qii; o1.w = pri + qir;

        float4* yo = (float4*)(yrow + c0);
        yo[0] = o0;
        yo[1] = o1;

        __syncwarp();   // all lanes done reading stage it%4 before it is reissued
    }
    #undef ISSUE_TILE
}

extern "C" void kernel_launch(void* const* d_in, const int* in_sizes, int n_in,
                              void* d_out, int out_size)
{
    const float2* X   = (const float2*)d_in[0];
    const float*  phi = (const float*)d_in[1];
    float2*       Y   = (float2*)d_out;

    dim3 grid(NCOLS / (WTILE * NWARP * TPW), NROWS);   // (128, 128)
    fir_cpdeep_kernel<<<grid, TBLOCK>>>(X, phi, Y);
}